// round 10
// baseline (speedup 1.0000x reference)
#include <cuda_runtime.h>
#include <cuda_bf16.h>
#include <cstdint>

#define BB  8
#define CC  512
#define HWD 1024
#define RR  8192   // BB*HWD

// Scratch (device globals — no runtime allocation allowed)
__device__ float        g_G[CC * CC];     // G[co][ci] = sum_k Wq[k][ci]*Wk[k][co]
__device__ __nv_bfloat16 g_t[RR * CC];    // t = xf @ G^T   (q' role)
__device__ __nv_bfloat16 g_xf[RR * CC];   // xf bf16        (k' role)
__device__ float g_vvec[CC], g_wvec[CC];  // v = Wk^T bq, w = Wq^T bk
__device__ float g_vd[RR], g_wd[RR];      // v.xf_j, w.xf_i per row
__device__ float g_gamma[1];              // bq.bk
__device__ unsigned int g_pmaxu[RR * BB]; // per-query, per-image max (orderable uint)
__device__ float g_gate[BB * HWD];        // softmax gate weights

// ============================================================================
// Helpers
// ============================================================================
__device__ __forceinline__ uint32_t smem_u32(const void* p) {
    uint32_t a;
    asm("{ .reg .u64 t; cvta.to.shared.u64 t, %1; cvt.u32.u64 %0, t; }"
        : "=r"(a) : "l"(p));
    return a;
}
__device__ __forceinline__ void cp_cg16(uint32_t s, const void* g) {
    asm volatile("cp.async.cg.shared.global [%0], [%1], 16;" :: "r"(s), "l"(g));
}
__device__ __forceinline__ void cp_commit() {
    asm volatile("cp.async.commit_group;" ::: "memory");
}
template <int N> __device__ __forceinline__ void cp_wait() {
    asm volatile("cp.async.wait_group %0;" :: "n"(N) : "memory");
}
__device__ __forceinline__ void mma_tf32_16n8k8(
    float* c, uint32_t a0, uint32_t a1, uint32_t a2, uint32_t a3,
    uint32_t b0, uint32_t b1)
{
    asm volatile(
        "mma.sync.aligned.m16n8k8.row.col.f32.tf32.tf32.f32 "
        "{%0,%1,%2,%3}, {%4,%5,%6,%7}, {%8,%9}, {%0,%1,%2,%3};"
        : "+f"(c[0]), "+f"(c[1]), "+f"(c[2]), "+f"(c[3])
        : "r"(a0), "r"(a1), "r"(a2), "r"(a3), "r"(b0), "r"(b1));
}
__device__ __forceinline__ void mma_bf16_16n8k16(
    float* c, const uint32_t* a, uint32_t b0, uint32_t b1)
{
    asm volatile(
        "mma.sync.aligned.m16n8k16.row.col.f32.bf16.bf16.f32 "
        "{%0,%1,%2,%3}, {%4,%5,%6,%7}, {%8,%9}, {%0,%1,%2,%3};"
        : "+f"(c[0]), "+f"(c[1]), "+f"(c[2]), "+f"(c[3])
        : "r"(a[0]), "r"(a[1]), "r"(a[2]), "r"(a[3]), "r"(b0), "r"(b1));
}
__device__ __forceinline__ void ldm_x4(uint32_t* r, uint32_t addr) {
    asm volatile("ldmatrix.sync.aligned.m8n8.x4.shared.b16 {%0,%1,%2,%3}, [%4];"
        : "=r"(r[0]), "=r"(r[1]), "=r"(r[2]), "=r"(r[3]) : "r"(addr));
}
__device__ __forceinline__ void tf32_split(float v, uint32_t& hi, uint32_t& lo) {
    uint32_t hb = __float_as_uint(v) & 0xFFFFE000u;
    hi = hb;
    lo = __float_as_uint(v - __uint_as_float(hb));
}
// Orderable encoding: float -> uint preserving order under unsigned compare.
__device__ __forceinline__ unsigned int fenc(float f) {
    unsigned int u = __float_as_uint(f);
    return (u & 0x80000000u) ? ~u : (u | 0x80000000u);
}
__device__ __forceinline__ float fdec(unsigned int u) {
    return __uint_as_float((u & 0x80000000u) ? (u & 0x7FFFFFFFu) : ~u);
}

#define SBK  32
#define PADR 36
#define PADK 136

// ============================================================================
// Kernel A: G = Wq^T-applied product + pmax init.  grid(16,16), 256 thr.
//   G[co][ci] = sum_k Wq[k][ci] * Wk[k][co]; also g_pmaxu[...] = enc(-1e30).
// ============================================================================
__global__ __launch_bounds__(256) void gemmG_kernel(
    const float* __restrict__ Wq, const float* __restrict__ Wk)
{
    __shared__ float As[16][32];
    __shared__ float Bs[16][32];
    const int co0 = blockIdx.x * 32;
    const int ci0 = blockIdx.y * 32;
    const int t = threadIdx.x;

    // pmax init: 256 blocks x 256 threads == RR*BB entries
    g_pmaxu[(blockIdx.y * 16 + blockIdx.x) * 256 + t] = fenc(-1e30f);

    float acc[2][2] = {{0.f,0.f},{0.f,0.f}};
    const int i0 = (t >> 4) * 2;
    const int j0 = (t & 15) * 2;

    for (int k0 = 0; k0 < CC; k0 += 16) {
        if (t < 128) {
            int kk = t >> 3, c4 = (t & 7) * 4;
            *(float4*)&As[kk][c4] = *(const float4*)(Wk + (size_t)(k0 + kk) * CC + co0 + c4);
        } else {
            int f = t - 128, kk = f >> 3, c4 = (f & 7) * 4;
            *(float4*)&Bs[kk][c4] = *(const float4*)(Wq + (size_t)(k0 + kk) * CC + ci0 + c4);
        }
        __syncthreads();
        #pragma unroll
        for (int kk = 0; kk < 16; kk++) {
            float a0 = As[kk][i0], a1 = As[kk][i0 + 1];
            float b0 = Bs[kk][j0], b1 = Bs[kk][j0 + 1];
            acc[0][0] += a0 * b0; acc[0][1] += a0 * b1;
            acc[1][0] += a1 * b0; acc[1][1] += a1 * b1;
        }
        __syncthreads();
    }
    #pragma unroll
    for (int di = 0; di < 2; di++)
        #pragma unroll
        for (int dj = 0; dj < 2; dj++)
            g_G[(size_t)(co0 + i0 + di) * CC + ci0 + j0 + dj] = acc[di][dj];
}

// ============================================================================
// Kernel B: v = Wk^T bq, w = Wq^T bk, gamma = bq.bk.  One block, 512 threads.
// ============================================================================
__global__ __launch_bounds__(512) void vw_kernel(
    const float* __restrict__ Wq, const float* __restrict__ Wk,
    const float* __restrict__ bq, const float* __restrict__ bk)
{
    const int t = threadIdx.x;
    float v = 0.f, w = 0.f;
    #pragma unroll 8
    for (int k = 0; k < CC; k++) {
        v += Wk[(size_t)k * CC + t] * bq[k];
        w += Wq[(size_t)k * CC + t] * bk[k];
    }
    g_vvec[t] = v;
    g_wvec[t] = w;

    __shared__ float red[512];
    red[t] = bq[t] * bk[t];
    __syncthreads();
    for (int s = 256; s > 0; s >>= 1) {
        if (t < s) red[t] += red[t + s];
        __syncthreads();
    }
    if (t == 0) g_gamma[0] = red[0];
}

// ============================================================================
// Kernel C (merged xpose + vdwd): one pass over x.
//   grid (32, 8): block = 32 pixels x 512 channels of image b.
//   Writes g_xf (bf16 transposed) and g_vd/g_wd.
// ============================================================================
__global__ __launch_bounds__(256) void prep_kernel(const float* __restrict__ x)
{
    __shared__ float tile[32][33];
    __shared__ float sv[8][32], sw[8][32];
    const int p0 = blockIdx.x * 32;
    const int b  = blockIdx.y;
    const int t  = threadIdx.x;
    const int tj = t & 31, ti = t >> 5;   // tj: pixel lane, ti: 0..7

    float a = 0.f, c = 0.f;

    for (int ct = 0; ct < 16; ct++) {
        const int c0 = ct * 32;
        #pragma unroll
        for (int rr = 0; rr < 4; rr++) {
            int i = rr * 8 + ti;
            tile[i][tj] = x[((size_t)b * CC + c0 + i) * HWD + p0 + tj];
        }
        __syncthreads();
        // transposed bf16 store (coalesced over 32 channels)
        #pragma unroll
        for (int rr = 0; rr < 4; rr++) {
            int pi = rr * 8 + ti;
            g_xf[((size_t)b * HWD + p0 + pi) * CC + c0 + tj] =
                __float2bfloat16(tile[tj][pi]);
        }
        // vd/wd accumulation: thread (ti,tj) covers channels c0+rr*8+ti of pixel tj
        #pragma unroll
        for (int rr = 0; rr < 4; rr++) {
            int i = rr * 8 + ti;
            float xv = tile[i][tj];
            a += g_vvec[c0 + i] * xv;
            c += g_wvec[c0 + i] * xv;
        }
        __syncthreads();
    }

    sv[ti][tj] = a;
    sw[ti][tj] = c;
    __syncthreads();
    if (ti == 0) {
        float va = 0.f, wa = 0.f;
        #pragma unroll
        for (int i = 0; i < 8; i++) { va += sv[i][tj]; wa += sw[i][tj]; }
        g_vd[b * HWD + p0 + tj] = va;
        g_wd[b * HWD + p0 + tj] = wa;
    }
}

// ============================================================================
// Kernel 1: t = xf @ G^T on tf32 mma (no bias), bf16 out.  grid (64, 4).
// ============================================================================
#define PJ_A_F (SBK * PADK)
#define PJ_B_F (128 * PADR)
#define PJ_SMEM (3 * (PJ_A_F + PJ_B_F) * 4)

__global__ __launch_bounds__(256, 2) void tproj_kernel(const float* __restrict__ x)
{
    extern __shared__ float sm[];
    const uint32_t sbase = smem_u32(sm);

    const int t    = threadIdx.x;
    const int lane = t & 31;
    const int wid  = t >> 5;
    const int wm   = wid >> 2;
    const int wn   = wid & 3;
    const int gid  = lane >> 2;
    const int tig  = lane & 3;

    const int r0  = blockIdx.x * 128;
    const int co0 = blockIdx.y * 128;
    const int b   = r0 / HWD;
    const int p0  = r0 % HWD;
    const float* xb = x + (size_t)b * CC * HWD;

    auto issue = [&](int c) {
        const int s  = c % 3;
        const int k0 = c * SBK;
        uint32_t As = sbase + (uint32_t)(s * PJ_A_F) * 4;
        #pragma unroll
        for (int u = 0; u < 4; u++) {
            int f = t + u * 256, kk = f >> 5, p4 = (f & 31) * 4;
            cp_cg16(As + (uint32_t)(kk * PADK + p4) * 4,
                    xb + (size_t)(k0 + kk) * HWD + p0 + p4);
        }
        uint32_t Bs = sbase + (uint32_t)(3 * PJ_A_F + s * PJ_B_F) * 4;
        #pragma unroll
        for (int u = 0; u < 4; u++) {
            int f = t + u * 256, n = f >> 3, c4 = (f & 7) * 4;
            cp_cg16(Bs + (uint32_t)(n * PADR + c4) * 4,
                    g_G + (size_t)(co0 + n) * CC + k0 + c4);
        }
        cp_commit();
    };

    float acc[4][4][4];
    #pragma unroll
    for (int mt = 0; mt < 4; mt++)
        #pragma unroll
        for (int nt = 0; nt < 4; nt++)
            #pragma unroll
            for (int v = 0; v < 4; v++) acc[mt][nt][v] = 0.f;

    issue(0); issue(1);
    for (int c = 0; c < 16; ++c) {
        if (c < 15) cp_wait<1>(); else cp_wait<0>();
        __syncthreads();
        if (c + 2 < 16) issue(c + 2);

        const float* Ab = sm + (c % 3) * PJ_A_F;
        const float* Bb = sm + 3 * PJ_A_F + (c % 3) * PJ_B_F;

        #pragma unroll
        for (int ks = 0; ks < 4; ++ks) {
            const int col = ks * 8 + tig;
            uint32_t a[4][4];
            #pragma unroll
            for (int mt = 0; mt < 4; ++mt) {
                int r = wm * 64 + mt * 16 + gid;
                a[mt][0] = __float_as_uint(Ab[col * PADK + r]);
                a[mt][1] = __float_as_uint(Ab[col * PADK + r + 8]);
                a[mt][2] = __float_as_uint(Ab[(col + 4) * PADK + r]);
                a[mt][3] = __float_as_uint(Ab[(col + 4) * PADK + r + 8]);
            }
            #pragma unroll
            for (int nt = 0; nt < 4; ++nt) {
                int n = wn * 32 + nt * 8 + gid;
                uint32_t b0 = __float_as_uint(Bb[n * PADR + col]);
                uint32_t b1 = __float_as_uint(Bb[n * PADR + col + 4]);
                #pragma unroll
                for (int mt = 0; mt < 4; ++mt)
                    mma_tf32_16n8k8(acc[mt][nt],
                                    a[mt][0], a[mt][1], a[mt][2], a[mt][3],
                                    b0, b1);
            }
        }
    }

    #pragma unroll
    for (int mt = 0; mt < 4; ++mt) {
        int row = r0 + wm * 64 + mt * 16 + gid;
        #pragma unroll
        for (int nt = 0; nt < 4; ++nt) {
            int co = co0 + wn * 32 + nt * 8 + tig * 2;
            __nv_bfloat162 v0, v1;
            v0.x = __float2bfloat16(acc[mt][nt][0]);
            v0.y = __float2bfloat16(acc[mt][nt][1]);
            v1.x = __float2bfloat16(acc[mt][nt][2]);
            v1.y = __float2bfloat16(acc[mt][nt][3]);
            *(__nv_bfloat162*)&g_t[(size_t)row * CC + co]       = v0;
            *(__nv_bfloat162*)&g_t[(size_t)(row + 8) * CC + co] = v1;
        }
    }
}

// ============================================================================
// Kernel 2: fused scores + per-image max.  grid = 2048 blocks:
//   block = (qt 0..63, img 0..7, pair 0..3) -> 128 queries x 256 keys,
//   16 K-chunks (2 ntl x 8 k64), 3-stage cp.async ring. Max combined across
//   key-blocks via orderable-uint atomicMax on g_pmaxu.
// ============================================================================
#define PB2 72                         // 64 + 8 pad bf16 elems / row
#define SC2_TILE  (128 * PB2 * 2)      // 18432
#define SC2_STAGE (2 * SC2_TILE)       // 36864
#define SC2_RED   (3 * SC2_STAGE)      // 110592
#define SC2_SMEM  (SC2_RED + 512 * 4)

__global__ __launch_bounds__(256, 2) void scores_mma_kernel()
{
    extern __shared__ char smc[];
    const uint32_t sbase = smem_u32(smc);

    const int t    = threadIdx.x;
    const int lane = t & 31;
    const int wid  = t >> 5;
    const int wm   = wid >> 2;
    const int wn   = wid & 3;
    const int gid  = lane >> 2;
    const int tig  = lane & 3;

    const int e    = blockIdx.x;
    const int qt   = e >> 5;             // 0..63
    const int img  = (e >> 2) & 7;       // 0..7
    const int pr   = e & 3;              // 0..3 (256-key group)
    const int q0   = qt * 128;
    const size_t kb = (size_t)img * HWD + (size_t)pr * 256;

    float* red = (float*)(smc + SC2_RED);
    const __nv_bfloat16* qp = g_t + (size_t)q0 * CC;
    const float* vdp = g_vd + img * HWD;

    const int lrow = lane & 15;
    const int lseg = (lane >> 4) * 8;

    auto issue = [&](int g) {
        const int s   = g % 3;
        const int ntl = g >> 3;              // 0..1
        const int k0  = (g & 7) * 64;
        uint32_t As = sbase + (uint32_t)(s * SC2_STAGE);
        #pragma unroll
        for (int u = 0; u < 4; u++) {
            int f = t + u * 256, r = f & 127, seg = f >> 7;
            cp_cg16(As + (uint32_t)(r * PB2 + seg * 8) * 2,
                    qp + (size_t)r * CC + k0 + seg * 8);
        }
        uint32_t Bs = As + SC2_TILE;
        const __nv_bfloat16* kp = g_xf + (kb + (size_t)ntl * 128) * CC;
        #pragma unroll
        for (int u = 0; u < 4; u++) {
            int f = t + u * 256, r = f & 127, seg = f >> 7;
            cp_cg16(Bs + (uint32_t)(r * PB2 + seg * 8) * 2,
                    kp + (size_t)r * CC + k0 + seg * 8);
        }
        cp_commit();
    };

    float acc[4][4][4];

    issue(0); issue(1);
    for (int g = 0; g < 16; ++g) {
        if (g < 15) cp_wait<1>(); else cp_wait<0>();
        __syncthreads();
        if (g + 2 < 16) issue(g + 2);

        if ((g & 7) == 0) {
            #pragma unroll
            for (int mt = 0; mt < 4; mt++)
                #pragma unroll
                for (int nt = 0; nt < 4; nt++)
                    #pragma unroll
                    for (int v = 0; v < 4; v++) acc[mt][nt][v] = 0.f;
        }

        const uint32_t Ab = sbase + (uint32_t)((g % 3) * SC2_STAGE);
        const uint32_t Bb = Ab + SC2_TILE;

        #pragma unroll
        for (int ks = 0; ks < 4; ++ks) {
            const int kcol = ks * 16 + lseg;
            uint32_t a[4][4];
            #pragma unroll
            for (int mt = 0; mt < 4; ++mt)
                ldm_x4(a[mt], Ab + (uint32_t)((wm * 64 + mt * 16 + lrow) * PB2 + kcol) * 2);
            uint32_t bf[2][4];
            #pragma unroll
            for (int nh = 0; nh < 2; ++nh)
                ldm_x4(bf[nh], Bb + (uint32_t)((wn * 32 + nh * 16 + lrow) * PB2 + kcol) * 2);
            #pragma unroll
            for (int nt = 0; nt < 4; ++nt) {
                uint32_t b0 = bf[nt >> 1][nt & 1];
                uint32_t b1 = bf[nt >> 1][(nt & 1) + 2];
                #pragma unroll
                for (int mt = 0; mt < 4; ++mt)
                    mma_bf16_16n8k16(acc[mt][nt], a[mt], b0, b1);
            }
        }

        if ((g & 7) == 7) {
            const int ntl = g >> 3;
            const int nb  = pr * 256 + ntl * 128 + wn * 32 + 2 * tig;
            float va[4], vb[4];
            #pragma unroll
            for (int nt = 0; nt < 4; nt++) {
                va[nt] = vdp[nb + nt * 8];
                vb[nt] = vdp[nb + nt * 8 + 1];
            }
            #pragma unroll
            for (int mt = 0; mt < 4; ++mt) {
                float m0 = -1e30f, m1 = -1e30f;
                #pragma unroll
                for (int nt = 0; nt < 4; ++nt) {
                    m0 = fmaxf(m0, fmaxf(acc[mt][nt][0] + va[nt], acc[mt][nt][1] + vb[nt]));
                    m1 = fmaxf(m1, fmaxf(acc[mt][nt][2] + va[nt], acc[mt][nt][3] + vb[nt]));
                }
                m0 = fmaxf(m0, __shfl_xor_sync(0xffffffffu, m0, 1));
                m0 = fmaxf(m0, __shfl_xor_sync(0xffffffffu, m0, 2));
                m1 = fmaxf(m1, __shfl_xor_sync(0xffffffffu, m1, 1));
                m1 = fmaxf(m1, __shfl_xor_sync(0xffffffffu, m1, 2));
                if (tig == 0) {
                    int r = wm * 64 + mt * 16 + gid;
                    red[wn * 128 + r]     = m0;
                    red[wn * 128 + r + 8] = m1;
                }
            }
            __syncthreads();
            if (t < 128) {
                float v = fmaxf(fmaxf(red[t], red[128 + t]),
                                fmaxf(red[256 + t], red[384 + t]));
                atomicMax(&g_pmaxu[(size_t)(q0 + t) * BB + img], fenc(v));
            }
            __syncthreads();
        }
    }
}

// ============================================================================
// Kernel 3: logits = (mean_img(pmax) + wd + gamma) / sqrt(C); softmax.
// ============================================================================
__global__ __launch_bounds__(256) void softmax_kernel()
{
    const int b = blockIdx.x;
    const int t = threadIdx.x;
    __shared__ float smr[256];
    __shared__ float logits[HWD];
    const float scale = 1.0f / sqrtf((float)CC);
    const float gamma = g_gamma[0];

    float lmax = -1e30f;
    for (int p = t; p < HWD; p += 256) {
        float s = 0.f;
        #pragma unroll
        for (int img = 0; img < BB; img++)
            s += fdec(g_pmaxu[(size_t)(b * HWD + p) * BB + img]);
        float lg = (s * (1.0f / BB) + g_wd[b * HWD + p] + gamma) * scale;
        logits[p] = lg;
        lmax = fmaxf(lmax, lg);
    }
    smr[t] = lmax; __syncthreads();
    for (int s = 128; s > 0; s >>= 1) {
        if (t < s) smr[t] = fmaxf(smr[t], smr[t + s]);
        __syncthreads();
    }
    float gmax = smr[0]; __syncthreads();

    float lsum = 0.f;
    for (int p = t; p < HWD; p += 256) {
        float e = expf(logits[p] - gmax);
        logits[p] = e;
        lsum += e;
    }
    smr[t] = lsum; __syncthreads();
    for (int s = 128; s > 0; s >>= 1) {
        if (t < s) smr[t] += smr[t + s];
        __syncthreads();
    }
    float inv = 1.0f / smr[0];
    for (int p = t; p < HWD; p += 256)
        g_gate[b * HWD + p] = logits[p] * inv;
}

// ============================================================================
// Kernel 4: gated output conv, 2-term tf32 split (Ahi.Bhi + Ahi.Blo).
// ============================================================================
__global__ __launch_bounds__(256, 2) void outconv_tc_kernel(
    const float* __restrict__ x, const float* __restrict__ W6,
    const float* __restrict__ b6, float* __restrict__ out)
{
    extern __shared__ float sm[];
    const uint32_t sbase = smem_u32(sm);

    const int t    = threadIdx.x;
    const int lane = t & 31;
    const int wid  = t >> 5;
    const int wm   = wid >> 2;
    const int wn   = wid & 3;
    const int gid  = lane >> 2;
    const int tig  = lane & 3;

    const int co0 = blockIdx.x * 128;
    const int p0  = blockIdx.y * 128;
    const int b   = blockIdx.z;
    const float* xb = x + (size_t)b * CC * HWD;

    auto issue = [&](int c) {
        const int s  = c % 3;
        const int k0 = c * SBK;
        uint32_t As = sbase + (uint32_t)(s * PJ_B_F) * 4;
        #pragma unroll
        for (int u = 0; u < 4; u++) {
            int f = t + u * 256, m = f >> 3, c4 = (f & 7) * 4;
            cp_cg16(As + (uint32_t)(m * PADR + c4) * 4,
                    W6 + (size_t)(co0 + m) * CC + k0 + c4);
        }
        uint32_t Bs = sbase + (uint32_t)(3 * PJ_B_F + s * PJ_A_F) * 4;
        #pragma unroll
        for (int u = 0; u < 4; u++) {
            int f = t + u * 256, kk = f >> 5, p4 = (f & 31) * 4;
            cp_cg16(Bs + (uint32_t)(kk * PADK + p4) * 4,
                    xb + (size_t)(k0 + kk) * HWD + p0 + p4);
        }
        cp_commit();
    };

    float acc[4][4][4];
    #pragma unroll
    for (int mt = 0; mt < 4; mt++)
        #pragma unroll
        for (int nt = 0; nt < 4; nt++)
            #pragma unroll
            for (int v = 0; v < 4; v++) acc[mt][nt][v] = 0.f;

    issue(0); issue(1);
    for (int c = 0; c < 16; ++c) {
        if (c < 15) cp_wait<1>(); else cp_wait<0>();
        __syncthreads();
        if (c + 2 < 16) issue(c + 2);

        const float* Ab = sm + (c % 3) * PJ_B_F;                 // [co][k]
        const float* Bb = sm + 3 * PJ_B_F + (c % 3) * PJ_A_F;    // [k][p]

        #pragma unroll
        for (int ks = 0; ks < 4; ++ks) {
            const int col = ks * 8 + tig;
            uint32_t ah[4][4];
            #pragma unroll
            for (int mt = 0; mt < 4; ++mt) {
                int m = wm * 64 + mt * 16 + gid;
                ah[mt][0] = __float_as_uint(Ab[m * PADR + col])           & 0xFFFFE000u;
                ah[mt][1] = __float_as_uint(Ab[(m + 8) * PADR + col])     & 0xFFFFE000u;
                ah[mt][2] = __float_as_uint(Ab[m * PADR + col + 4])       & 0xFFFFE000u;
                ah[mt][3] = __float_as_uint(Ab[(m + 8) * PADR + col + 4]) & 0xFFFFE000u;
            }
            #pragma unroll
            for (int nt = 0; nt < 4; ++nt) {
                int n = wn * 32 + nt * 8 + gid;
                uint32_t bh0, bl0, bh1, bl1;
                tf32_split(Bb[col * PADK + n],       bh0, bl0);
                tf32_split(Bb[(col + 4) * PADK + n], bh1, bl1);
                #pragma unroll
                for (int mt = 0; mt < 4; ++mt) {
                    mma_tf32_16n8k8(acc[mt][nt],
                                    ah[mt][0], ah[mt][1], ah[mt][2], ah[mt][3],
                                    bh0, bh1);
                    mma_tf32_16n8k8(acc[mt][nt],
                                    ah[mt][0], ah[mt][1], ah[mt][2], ah[mt][3],
                                    bl0, bl1);
                }
            }
        }
    }

    #pragma unroll
    for (int mt = 0; mt < 4; ++mt) {
        int co = co0 + wm * 64 + mt * 16 + gid;
        float bs0 = b6[co], bs1 = b6[co + 8];
        #pragma unroll
        for (int nt = 0; nt < 4; ++nt) {
            int p = p0 + wn * 32 + nt * 8 + tig * 2;
            float g0 = g_gate[b * HWD + p];
            float g1 = g_gate[b * HWD + p + 1];
            float2 o0 = { acc[mt][nt][0] * g0 + bs0, acc[mt][nt][1] * g1 + bs0 };
            float2 o1 = { acc[mt][nt][2] * g0 + bs1, acc[mt][nt][3] * g1 + bs1 };
            *(float2*)&out[((size_t)(b * CC + co)) * HWD + p]     = o0;
            *(float2*)&out[((size_t)(b * CC + co + 8)) * HWD + p] = o1;
        }
    }
}

// ============================================================================
extern "C" void kernel_launch(void* const* d_in, const int* in_sizes, int n_in,
                              void* d_out, int out_size)
{
    const float* x  = (const float*)d_in[0];
    const float* Wq = (const float*)d_in[1];
    const float* bq = (const float*)d_in[2];
    const float* Wk = (const float*)d_in[3];
    const float* bk = (const float*)d_in[4];
    const float* W6 = (const float*)d_in[5];
    const float* b6 = (const float*)d_in[6];
    float* out = (float*)d_out;

    cudaFuncSetAttribute(tproj_kernel,
                         cudaFuncAttributeMaxDynamicSharedMemorySize, PJ_SMEM);
    cudaFuncSetAttribute(scores_mma_kernel,
                         cudaFuncAttributeMaxDynamicSharedMemorySize, SC2_SMEM);
    cudaFuncSetAttribute(outconv_tc_kernel,
                         cudaFuncAttributeMaxDynamicSharedMemorySize, PJ_SMEM);

    gemmG_kernel<<<dim3(16, 16), 256>>>(Wq, Wk);
    vw_kernel<<<1, 512>>>(Wq, Wk, bq, bk);
    prep_kernel<<<dim3(32, 8), 256>>>(x);
    tproj_kernel<<<dim3(64, 4), 256, PJ_SMEM>>>(x);
    scores_mma_kernel<<<2048, 256, SC2_SMEM>>>();
    softmax_kernel<<<8, 256>>>();
    outconv_tc_kernel<<<dim3(4, 8, 8), 256, PJ_SMEM>>>(x, W6, b6, out);
}

// round 11
// speedup vs baseline: 1.5233x; 1.5233x over previous
#include <cuda_runtime.h>
#include <cuda_bf16.h>
#include <cstdint>

#define BB  8
#define CC  512
#define HWD 1024
#define RR  8192   // BB*HWD

// Scratch (device globals — no runtime allocation allowed)
__device__ __nv_bfloat16 g_q[RR * CC];   // bf16 projections (8 MB each)
__device__ __nv_bfloat16 g_k[RR * CC];
__device__ float g_pmax[RR * BB];        // per-query, per-image max score
__device__ float g_w[BB * HWD];          // softmax gate weights

// ============================================================================
// Helpers
// ============================================================================
__device__ __forceinline__ uint32_t smem_u32(const void* p) {
    uint32_t a;
    asm("{ .reg .u64 t; cvta.to.shared.u64 t, %1; cvt.u32.u64 %0, t; }"
        : "=r"(a) : "l"(p));
    return a;
}
__device__ __forceinline__ void cp_cg16(uint32_t s, const void* g) {
    asm volatile("cp.async.cg.shared.global [%0], [%1], 16;" :: "r"(s), "l"(g));
}
__device__ __forceinline__ void cp_commit() {
    asm volatile("cp.async.commit_group;" ::: "memory");
}
template <int N> __device__ __forceinline__ void cp_wait() {
    asm volatile("cp.async.wait_group %0;" :: "n"(N) : "memory");
}
__device__ __forceinline__ void mma_tf32_16n8k8(
    float* c, uint32_t a0, uint32_t a1, uint32_t a2, uint32_t a3,
    uint32_t b0, uint32_t b1)
{
    asm volatile(
        "mma.sync.aligned.m16n8k8.row.col.f32.tf32.tf32.f32 "
        "{%0,%1,%2,%3}, {%4,%5,%6,%7}, {%8,%9}, {%0,%1,%2,%3};"
        : "+f"(c[0]), "+f"(c[1]), "+f"(c[2]), "+f"(c[3])
        : "r"(a0), "r"(a1), "r"(a2), "r"(a3), "r"(b0), "r"(b1));
}
__device__ __forceinline__ void mma_bf16_16n8k16(
    float* c, const uint32_t* a, uint32_t b0, uint32_t b1)
{
    asm volatile(
        "mma.sync.aligned.m16n8k16.row.col.f32.bf16.bf16.f32 "
        "{%0,%1,%2,%3}, {%4,%5,%6,%7}, {%8,%9}, {%0,%1,%2,%3};"
        : "+f"(c[0]), "+f"(c[1]), "+f"(c[2]), "+f"(c[3])
        : "r"(a[0]), "r"(a[1]), "r"(a[2]), "r"(a[3]), "r"(b0), "r"(b1));
}
__device__ __forceinline__ void ldm_x4(uint32_t* r, uint32_t addr) {
    asm volatile("ldmatrix.sync.aligned.m8n8.x4.shared.b16 {%0,%1,%2,%3}, [%4];"
        : "=r"(r[0]), "=r"(r[1]), "=r"(r[2]), "=r"(r[3]) : "r"(addr));
}
__device__ __forceinline__ void tf32_split(float v, uint32_t& hi, uint32_t& lo) {
    uint32_t hb = __float_as_uint(v) & 0xFFFFE000u;
    hi = hb;
    lo = __float_as_uint(v - __uint_as_float(hb));
}

// Shared tiling constants (all GEMM kernels: 256 threads, 8 warps)
#define SBK  32      // K-chunk
#define PADR 36      // fp32 [rows][k] pad (proj/outconv)
#define PADK 136     // fp32 [k][cols] pad

// ============================================================================
// Kernel 1: q/k projection on tf32 mma.sync. grid (64, 4, 2). 2 CTAs/SM.
//   Epilogue converts to bf16 and stores to g_q/g_k.
// ============================================================================
#define PJ_A_F (SBK * PADK)          // 4352 floats / stage
#define PJ_B_F (128 * PADR)          // 4608 floats / stage
#define PJ_SMEM (3 * (PJ_A_F + PJ_B_F) * 4)

__global__ __launch_bounds__(256, 2) void proj_tc_kernel(
    const float* __restrict__ x,
    const float* __restrict__ Wq, const float* __restrict__ bq,
    const float* __restrict__ Wk, const float* __restrict__ bk)
{
    extern __shared__ float sm[];
    const uint32_t sbase = smem_u32(sm);

    const int dst = blockIdx.z;
    const float* W    = dst ? Wk : Wq;
    const float* bias = dst ? bk : bq;
    __nv_bfloat16* out = dst ? g_k : g_q;

    const int t    = threadIdx.x;
    const int lane = t & 31;
    const int wid  = t >> 5;
    const int wm   = wid >> 2;
    const int wn   = wid & 3;
    const int gid  = lane >> 2;
    const int tig  = lane & 3;

    const int r0  = blockIdx.x * 128;
    const int co0 = blockIdx.y * 128;
    const int b   = r0 / HWD;
    const int p0  = r0 % HWD;
    const float* xb = x + (size_t)b * CC * HWD;

    auto issue = [&](int c) {
        const int s  = c % 3;
        const int k0 = c * SBK;
        uint32_t As = sbase + (uint32_t)(s * PJ_A_F) * 4;
        #pragma unroll
        for (int u = 0; u < 4; u++) {
            int f = t + u * 256, kk = f >> 5, p4 = (f & 31) * 4;
            cp_cg16(As + (uint32_t)(kk * PADK + p4) * 4,
                    xb + (size_t)(k0 + kk) * HWD + p0 + p4);
        }
        uint32_t Bs = sbase + (uint32_t)(3 * PJ_A_F + s * PJ_B_F) * 4;
        #pragma unroll
        for (int u = 0; u < 4; u++) {
            int f = t + u * 256, n = f >> 3, c4 = (f & 7) * 4;
            cp_cg16(Bs + (uint32_t)(n * PADR + c4) * 4,
                    W + (size_t)(co0 + n) * CC + k0 + c4);
        }
        cp_commit();
    };

    float acc[4][4][4];
    #pragma unroll
    for (int mt = 0; mt < 4; mt++)
        #pragma unroll
        for (int nt = 0; nt < 4; nt++)
            #pragma unroll
            for (int v = 0; v < 4; v++) acc[mt][nt][v] = 0.f;

    issue(0); issue(1);
    for (int c = 0; c < 16; ++c) {
        if (c < 15) cp_wait<1>(); else cp_wait<0>();
        __syncthreads();
        if (c + 2 < 16) issue(c + 2);

        const float* Ab = sm + (c % 3) * PJ_A_F;                 // [k][p]
        const float* Bb = sm + 3 * PJ_A_F + (c % 3) * PJ_B_F;    // [co][k]

        #pragma unroll
        for (int ks = 0; ks < 4; ++ks) {
            const int col = ks * 8 + tig;
            uint32_t a[4][4];
            #pragma unroll
            for (int mt = 0; mt < 4; ++mt) {
                int r = wm * 64 + mt * 16 + gid;
                a[mt][0] = __float_as_uint(Ab[col * PADK + r]);
                a[mt][1] = __float_as_uint(Ab[col * PADK + r + 8]);
                a[mt][2] = __float_as_uint(Ab[(col + 4) * PADK + r]);
                a[mt][3] = __float_as_uint(Ab[(col + 4) * PADK + r + 8]);
            }
            #pragma unroll
            for (int nt = 0; nt < 4; ++nt) {
                int n = wn * 32 + nt * 8 + gid;
                uint32_t b0 = __float_as_uint(Bb[n * PADR + col]);
                uint32_t b1 = __float_as_uint(Bb[n * PADR + col + 4]);
                #pragma unroll
                for (int mt = 0; mt < 4; ++mt)
                    mma_tf32_16n8k8(acc[mt][nt],
                                    a[mt][0], a[mt][1], a[mt][2], a[mt][3],
                                    b0, b1);
            }
        }
    }

    #pragma unroll
    for (int mt = 0; mt < 4; ++mt) {
        int row = r0 + wm * 64 + mt * 16 + gid;
        #pragma unroll
        for (int nt = 0; nt < 4; ++nt) {
            int co = co0 + wn * 32 + nt * 8 + tig * 2;
            float bs0 = bias[co], bs1 = bias[co + 1];
            __nv_bfloat162 v0, v1;
            v0.x = __float2bfloat16(acc[mt][nt][0] + bs0);
            v0.y = __float2bfloat16(acc[mt][nt][1] + bs1);
            v1.x = __float2bfloat16(acc[mt][nt][2] + bs0);
            v1.y = __float2bfloat16(acc[mt][nt][3] + bs1);
            *(__nv_bfloat162*)&out[(size_t)row * CC + co]       = v0;
            *(__nv_bfloat162*)&out[(size_t)(row + 8) * CC + co] = v1;
        }
    }
}

// ============================================================================
// Kernel 2: fused scores + per-image max via bf16 mma (m16n8k16) + ldmatrix.
//   grid (64, 8). Block: 128 queries x 1024 keys (one image), N-tile = 128
//   (8 N-tiles x 16 K-chunks = 128 chunks), 3-stage cp.async ring.
//   80B row pitch -> conflict-free ldmatrix/STS. 2 CTAs/SM.
// ============================================================================
#define PB 40                         // bf16 elems per smem row (32 + 8 pad)
#define SC_TILE_B (128 * PB * 2)      // 10240 bytes (A or B tile)
#define SC_STAGE_B (2 * SC_TILE_B)    // 20480
#define SC_RED_OFF (3 * SC_STAGE_B)   // 61440
#define SC_SMEM (SC_RED_OFF + 512 * 4)

__global__ __launch_bounds__(256, 2) void scores_mma_kernel()
{
    extern __shared__ char smc[];
    const uint32_t sbase = smem_u32(smc);

    const int t    = threadIdx.x;
    const int lane = t & 31;
    const int wid  = t >> 5;
    const int wm   = wid >> 2;
    const int wn   = wid & 3;
    const int gid  = lane >> 2;
    const int tig  = lane & 3;
    const int q0   = blockIdx.x * 128;
    const size_t kb = (size_t)blockIdx.y * HWD;

    float* red = (float*)(smc + SC_RED_OFF);
    float qm = -1e30f;
    const __nv_bfloat16* qp = g_q + (size_t)q0 * CC;

    // ldmatrix lane address components
    const int lrow = lane & 15;
    const int lseg = (lane >> 4) * 8;

    auto issue = [&](int g) {
        const int s   = g % 3;
        const int ntl = g >> 4;
        const int k0  = (g & 15) * SBK;
        uint32_t As = sbase + (uint32_t)(s * SC_STAGE_B);
        #pragma unroll
        for (int u = 0; u < 2; u++) {
            int f = t + u * 256, r = f & 127, seg = f >> 7;   // conflict-free STS
            cp_cg16(As + (uint32_t)(r * PB + seg * 8) * 2,
                    qp + (size_t)r * CC + k0 + seg * 8);
        }
        uint32_t Bs = As + SC_TILE_B;
        const __nv_bfloat16* kp = g_k + (kb + (size_t)ntl * 128) * CC;
        #pragma unroll
        for (int u = 0; u < 2; u++) {
            int f = t + u * 256, r = f & 127, seg = f >> 7;
            cp_cg16(Bs + (uint32_t)(r * PB + seg * 8) * 2,
                    kp + (size_t)r * CC + k0 + seg * 8);
        }
        cp_commit();
    };

    float acc[4][4][4];

    issue(0); issue(1);
    for (int g = 0; g < 128; ++g) {
        if ((g & 15) == 0) {
            #pragma unroll
            for (int mt = 0; mt < 4; mt++)
                #pragma unroll
                for (int nt = 0; nt < 4; nt++)
                    #pragma unroll
                    for (int v = 0; v < 4; v++) acc[mt][nt][v] = 0.f;
        }
        if (g < 127) cp_wait<1>(); else cp_wait<0>();
        __syncthreads();
        if (g + 2 < 128) issue(g + 2);

        const uint32_t Ab = sbase + (uint32_t)((g % 3) * SC_STAGE_B);
        const uint32_t Bb = Ab + SC_TILE_B;

        #pragma unroll
        for (int ks = 0; ks < 2; ++ks) {
            const int kcol = ks * 16 + lseg;
            uint32_t a[4][4];
            #pragma unroll
            for (int mt = 0; mt < 4; ++mt)
                ldm_x4(a[mt], Ab + (uint32_t)((wm * 64 + mt * 16 + lrow) * PB + kcol) * 2);
            uint32_t bf[2][4];
            #pragma unroll
            for (int nh = 0; nh < 2; ++nh)
                ldm_x4(bf[nh], Bb + (uint32_t)((wn * 32 + nh * 16 + lrow) * PB + kcol) * 2);
            #pragma unroll
            for (int nt = 0; nt < 4; ++nt) {
                uint32_t b0 = bf[nt >> 1][nt & 1];
                uint32_t b1 = bf[nt >> 1][(nt & 1) + 2];
                #pragma unroll
                for (int mt = 0; mt < 4; ++mt)
                    mma_bf16_16n8k16(acc[mt][nt], a[mt], b0, b1);
            }
        }

        if ((g & 15) == 15) {
            #pragma unroll
            for (int mt = 0; mt < 4; ++mt) {
                float m0 = -1e30f, m1 = -1e30f;
                #pragma unroll
                for (int nt = 0; nt < 4; ++nt) {
                    m0 = fmaxf(m0, fmaxf(acc[mt][nt][0], acc[mt][nt][1]));
                    m1 = fmaxf(m1, fmaxf(acc[mt][nt][2], acc[mt][nt][3]));
                }
                m0 = fmaxf(m0, __shfl_xor_sync(0xffffffffu, m0, 1));
                m0 = fmaxf(m0, __shfl_xor_sync(0xffffffffu, m0, 2));
                m1 = fmaxf(m1, __shfl_xor_sync(0xffffffffu, m1, 1));
                m1 = fmaxf(m1, __shfl_xor_sync(0xffffffffu, m1, 2));
                if (tig == 0) {
                    int r = wm * 64 + mt * 16 + gid;
                    red[wn * 128 + r]     = m0;
                    red[wn * 128 + r + 8] = m1;
                }
            }
            __syncthreads();
            if (t < 128) {
                float v = fmaxf(fmaxf(red[t], red[128 + t]),
                                fmaxf(red[256 + t], red[384 + t]));
                qm = fmaxf(qm, v);
            }
            __syncthreads();
        }
    }

    if (t < 128)
        g_pmax[(size_t)(q0 + t) * BB + blockIdx.y] = qm;
}

// ============================================================================
// Kernel 3: logits = mean-over-images(pmax) / sqrt(C); softmax per batch.
// ============================================================================
__global__ __launch_bounds__(256) void softmax_kernel()
{
    const int b = blockIdx.x;
    const int t = threadIdx.x;
    __shared__ float smr[256];
    __shared__ float logits[HWD];
    const float scale = 1.0f / sqrtf((float)CC);

    float lmax = -1e30f;
    for (int p = t; p < HWD; p += 256) {
        float s = 0.f;
        #pragma unroll
        for (int img = 0; img < BB; img++)
            s += g_pmax[(size_t)(b * HWD + p) * BB + img];
        float lg = s * (1.0f / BB) * scale;
        logits[p] = lg;
        lmax = fmaxf(lmax, lg);
    }
    smr[t] = lmax; __syncthreads();
    for (int s = 128; s > 0; s >>= 1) {
        if (t < s) smr[t] = fmaxf(smr[t], smr[t + s]);
        __syncthreads();
    }
    float gmax = smr[0]; __syncthreads();

    float lsum = 0.f;
    for (int p = t; p < HWD; p += 256) {
        float e = expf(logits[p] - gmax);
        logits[p] = e;
        lsum += e;
    }
    smr[t] = lsum; __syncthreads();
    for (int s = 128; s > 0; s >>= 1) {
        if (t < s) smr[t] += smr[t + s];
        __syncthreads();
    }
    float inv = 1.0f / smr[0];
    for (int p = t; p < HWD; p += 256)
        g_w[b * HWD + p] = logits[p] * inv;
}

// ============================================================================
// Kernel 4: gated output conv, 2-term tf32 split (Ahi.Bhi + Ahi.Blo).
//   grid (4, 8, 8). 2 CTAs/SM.
// ============================================================================
__global__ __launch_bounds__(256, 2) void outconv_tc_kernel(
    const float* __restrict__ x, const float* __restrict__ W6,
    const float* __restrict__ b6, float* __restrict__ out)
{
    extern __shared__ float sm[];
    const uint32_t sbase = smem_u32(sm);

    const int t    = threadIdx.x;
    const int lane = t & 31;
    const int wid  = t >> 5;
    const int wm   = wid >> 2;
    const int wn   = wid & 3;
    const int gid  = lane >> 2;
    const int tig  = lane & 3;

    const int co0 = blockIdx.x * 128;
    const int p0  = blockIdx.y * 128;
    const int b   = blockIdx.z;
    const float* xb = x + (size_t)b * CC * HWD;

    auto issue = [&](int c) {
        const int s  = c % 3;
        const int k0 = c * SBK;
        uint32_t As = sbase + (uint32_t)(s * PJ_B_F) * 4;      // [co][k] PADR
        #pragma unroll
        for (int u = 0; u < 4; u++) {
            int f = t + u * 256, m = f >> 3, c4 = (f & 7) * 4;
            cp_cg16(As + (uint32_t)(m * PADR + c4) * 4,
                    W6 + (size_t)(co0 + m) * CC + k0 + c4);
        }
        uint32_t Bs = sbase + (uint32_t)(3 * PJ_B_F + s * PJ_A_F) * 4;  // [k][p] PADK
        #pragma unroll
        for (int u = 0; u < 4; u++) {
            int f = t + u * 256, kk = f >> 5, p4 = (f & 31) * 4;
            cp_cg16(Bs + (uint32_t)(kk * PADK + p4) * 4,
                    xb + (size_t)(k0 + kk) * HWD + p0 + p4);
        }
        cp_commit();
    };

    float acc[4][4][4];
    #pragma unroll
    for (int mt = 0; mt < 4; mt++)
        #pragma unroll
        for (int nt = 0; nt < 4; nt++)
            #pragma unroll
            for (int v = 0; v < 4; v++) acc[mt][nt][v] = 0.f;

    issue(0); issue(1);
    for (int c = 0; c < 16; ++c) {
        if (c < 15) cp_wait<1>(); else cp_wait<0>();
        __syncthreads();
        if (c + 2 < 16) issue(c + 2);

        const float* Ab = sm + (c % 3) * PJ_B_F;                 // [co][k]
        const float* Bb = sm + 3 * PJ_B_F + (c % 3) * PJ_A_F;    // [k][p]

        #pragma unroll
        for (int ks = 0; ks < 4; ++ks) {
            const int col = ks * 8 + tig;
            uint32_t ah[4][4];
            #pragma unroll
            for (int mt = 0; mt < 4; ++mt) {
                int m = wm * 64 + mt * 16 + gid;
                ah[mt][0] = __float_as_uint(Ab[m * PADR + col])           & 0xFFFFE000u;
                ah[mt][1] = __float_as_uint(Ab[(m + 8) * PADR + col])     & 0xFFFFE000u;
                ah[mt][2] = __float_as_uint(Ab[m * PADR + col + 4])       & 0xFFFFE000u;
                ah[mt][3] = __float_as_uint(Ab[(m + 8) * PADR + col + 4]) & 0xFFFFE000u;
            }
            #pragma unroll
            for (int nt = 0; nt < 4; ++nt) {
                int n = wn * 32 + nt * 8 + gid;
                uint32_t bh0, bl0, bh1, bl1;
                tf32_split(Bb[col * PADK + n],       bh0, bl0);
                tf32_split(Bb[(col + 4) * PADK + n], bh1, bl1);
                #pragma unroll
                for (int mt = 0; mt < 4; ++mt) {
                    mma_tf32_16n8k8(acc[mt][nt],
                                    ah[mt][0], ah[mt][1], ah[mt][2], ah[mt][3],
                                    bh0, bh1);
                    mma_tf32_16n8k8(acc[mt][nt],
                                    ah[mt][0], ah[mt][1], ah[mt][2], ah[mt][3],
                                    bl0, bl1);
                }
            }
        }
    }

    #pragma unroll
    for (int mt = 0; mt < 4; ++mt) {
        int co = co0 + wm * 64 + mt * 16 + gid;
        float bs0 = b6[co], bs1 = b6[co + 8];
        #pragma unroll
        for (int nt = 0; nt < 4; ++nt) {
            int p = p0 + wn * 32 + nt * 8 + tig * 2;
            float g0 = g_w[b * HWD + p];
            float g1 = g_w[b * HWD + p + 1];
            float2 o0 = { acc[mt][nt][0] * g0 + bs0, acc[mt][nt][1] * g1 + bs0 };
            float2 o1 = { acc[mt][nt][2] * g0 + bs1, acc[mt][nt][3] * g1 + bs1 };
            *(float2*)&out[((size_t)(b * CC + co)) * HWD + p]     = o0;
            *(float2*)&out[((size_t)(b * CC + co + 8)) * HWD + p] = o1;
        }
    }
}

// ============================================================================
extern "C" void kernel_launch(void* const* d_in, const int* in_sizes, int n_in,
                              void* d_out, int out_size)
{
    const float* x  = (const float*)d_in[0];
    const float* Wq = (const float*)d_in[1];
    const float* bq = (const float*)d_in[2];
    const float* Wk = (const float*)d_in[3];
    const float* bk = (const float*)d_in[4];
    const float* W6 = (const float*)d_in[5];
    const float* b6 = (const float*)d_in[6];
    float* out = (float*)d_out;

    cudaFuncSetAttribute(proj_tc_kernel,
                         cudaFuncAttributeMaxDynamicSharedMemorySize, PJ_SMEM);
    cudaFuncSetAttribute(scores_mma_kernel,
                         cudaFuncAttributeMaxDynamicSharedMemorySize, SC_SMEM);
    cudaFuncSetAttribute(outconv_tc_kernel,
                         cudaFuncAttributeMaxDynamicSharedMemorySize, PJ_SMEM);

    dim3 blk(256);
    proj_tc_kernel<<<dim3(RR / 128, CC / 128, 2), blk, PJ_SMEM>>>(x, Wq, bq, Wk, bk);
    scores_mma_kernel<<<dim3(RR / 128, BB), blk, SC_SMEM>>>();
    softmax_kernel<<<BB, blk>>>();
    outconv_tc_kernel<<<dim3(CC / 128, HWD / 128, BB), blk, PJ_SMEM>>>(x, W6, b6, out);
}

// round 12
// speedup vs baseline: 1.6625x; 1.0914x over previous
#include <cuda_runtime.h>
#include <cuda_bf16.h>
#include <cstdint>

#define BB  8
#define CC  512
#define HWD 1024
#define RR  8192   // BB*HWD

// Scratch (device globals — no runtime allocation allowed)
__device__ __nv_bfloat16 g_q[RR * CC];   // bf16 projections (8 MB each)
__device__ __nv_bfloat16 g_k[RR * CC];
__device__ unsigned int g_pmaxu[RR * BB]; // per-query, per-image max (orderable uint)
__device__ float g_w[BB * HWD];          // softmax gate weights

// ============================================================================
// Helpers
// ============================================================================
__device__ __forceinline__ uint32_t smem_u32(const void* p) {
    uint32_t a;
    asm("{ .reg .u64 t; cvta.to.shared.u64 t, %1; cvt.u32.u64 %0, t; }"
        : "=r"(a) : "l"(p));
    return a;
}
__device__ __forceinline__ void cp_cg16(uint32_t s, const void* g) {
    asm volatile("cp.async.cg.shared.global [%0], [%1], 16;" :: "r"(s), "l"(g));
}
__device__ __forceinline__ void cp_commit() {
    asm volatile("cp.async.commit_group;" ::: "memory");
}
template <int N> __device__ __forceinline__ void cp_wait() {
    asm volatile("cp.async.wait_group %0;" :: "n"(N) : "memory");
}
__device__ __forceinline__ void mma_tf32_16n8k8(
    float* c, uint32_t a0, uint32_t a1, uint32_t a2, uint32_t a3,
    uint32_t b0, uint32_t b1)
{
    asm volatile(
        "mma.sync.aligned.m16n8k8.row.col.f32.tf32.tf32.f32 "
        "{%0,%1,%2,%3}, {%4,%5,%6,%7}, {%8,%9}, {%0,%1,%2,%3};"
        : "+f"(c[0]), "+f"(c[1]), "+f"(c[2]), "+f"(c[3])
        : "r"(a0), "r"(a1), "r"(a2), "r"(a3), "r"(b0), "r"(b1));
}
__device__ __forceinline__ void mma_bf16_16n8k16(
    float* c, const uint32_t* a, uint32_t b0, uint32_t b1)
{
    asm volatile(
        "mma.sync.aligned.m16n8k16.row.col.f32.bf16.bf16.f32 "
        "{%0,%1,%2,%3}, {%4,%5,%6,%7}, {%8,%9}, {%0,%1,%2,%3};"
        : "+f"(c[0]), "+f"(c[1]), "+f"(c[2]), "+f"(c[3])
        : "r"(a[0]), "r"(a[1]), "r"(a[2]), "r"(a[3]), "r"(b0), "r"(b1));
}
__device__ __forceinline__ void ldm_x4(uint32_t* r, uint32_t addr) {
    asm volatile("ldmatrix.sync.aligned.m8n8.x4.shared.b16 {%0,%1,%2,%3}, [%4];"
        : "=r"(r[0]), "=r"(r[1]), "=r"(r[2]), "=r"(r[3]) : "r"(addr));
}
__device__ __forceinline__ void tf32_split(float v, uint32_t& hi, uint32_t& lo) {
    uint32_t hb = __float_as_uint(v) & 0xFFFFE000u;
    hi = hb;
    lo = __float_as_uint(v - __uint_as_float(hb));
}
// Orderable encoding: float -> uint preserving order under unsigned compare.
__device__ __forceinline__ unsigned int fenc(float f) {
    unsigned int u = __float_as_uint(f);
    return (u & 0x80000000u) ? ~u : (u | 0x80000000u);
}
__device__ __forceinline__ float fdec(unsigned int u) {
    return __uint_as_float((u & 0x80000000u) ? (u & 0x7FFFFFFFu) : ~u);
}

// Shared tiling constants (all GEMM kernels: 256 threads, 8 warps)
#define SBK  32      // K-chunk
#define PADR 36      // fp32 [rows][k] pad (proj/outconv)
#define PADK 136     // fp32 [k][cols] pad

// ============================================================================
// Kernel 1: q/k projection on tf32 mma.sync. grid (64, 4, 2). 2 CTAs/SM.
//   Epilogue converts to bf16 and stores to g_q/g_k. z==0 blocks also init
//   g_pmaxu (64*4 blocks x 256 threads == RR*BB entries exactly).
// ============================================================================
#define PJ_A_F (SBK * PADK)          // 4352 floats / stage
#define PJ_B_F (128 * PADR)          // 4608 floats / stage
#define PJ_SMEM (3 * (PJ_A_F + PJ_B_F) * 4)

__global__ __launch_bounds__(256, 2) void proj_tc_kernel(
    const float* __restrict__ x,
    const float* __restrict__ Wq, const float* __restrict__ bq,
    const float* __restrict__ Wk, const float* __restrict__ bk)
{
    extern __shared__ float sm[];
    const uint32_t sbase = smem_u32(sm);

    const int dst = blockIdx.z;
    const float* W    = dst ? Wk : Wq;
    const float* bias = dst ? bk : bq;
    __nv_bfloat16* out = dst ? g_k : g_q;

    const int t    = threadIdx.x;
    const int lane = t & 31;
    const int wid  = t >> 5;
    const int wm   = wid >> 2;
    const int wn   = wid & 3;
    const int gid  = lane >> 2;
    const int tig  = lane & 3;

    if (dst == 0) {
        int lin = (blockIdx.x * 4 + blockIdx.y) * 256 + t;
        g_pmaxu[lin] = fenc(-1e30f);
    }

    const int r0  = blockIdx.x * 128;
    const int co0 = blockIdx.y * 128;
    const int b   = r0 / HWD;
    const int p0  = r0 % HWD;
    const float* xb = x + (size_t)b * CC * HWD;

    auto issue = [&](int c) {
        const int s  = c % 3;
        const int k0 = c * SBK;
        uint32_t As = sbase + (uint32_t)(s * PJ_A_F) * 4;
        #pragma unroll
        for (int u = 0; u < 4; u++) {
            int f = t + u * 256, kk = f >> 5, p4 = (f & 31) * 4;
            cp_cg16(As + (uint32_t)(kk * PADK + p4) * 4,
                    xb + (size_t)(k0 + kk) * HWD + p0 + p4);
        }
        uint32_t Bs = sbase + (uint32_t)(3 * PJ_A_F + s * PJ_B_F) * 4;
        #pragma unroll
        for (int u = 0; u < 4; u++) {
            int f = t + u * 256, n = f >> 3, c4 = (f & 7) * 4;
            cp_cg16(Bs + (uint32_t)(n * PADR + c4) * 4,
                    W + (size_t)(co0 + n) * CC + k0 + c4);
        }
        cp_commit();
    };

    float acc[4][4][4];
    #pragma unroll
    for (int mt = 0; mt < 4; mt++)
        #pragma unroll
        for (int nt = 0; nt < 4; nt++)
            #pragma unroll
            for (int v = 0; v < 4; v++) acc[mt][nt][v] = 0.f;

    issue(0); issue(1);
    for (int c = 0; c < 16; ++c) {
        if (c < 15) cp_wait<1>(); else cp_wait<0>();
        __syncthreads();
        if (c + 2 < 16) issue(c + 2);

        const float* Ab = sm + (c % 3) * PJ_A_F;                 // [k][p]
        const float* Bb = sm + 3 * PJ_A_F + (c % 3) * PJ_B_F;    // [co][k]

        #pragma unroll
        for (int ks = 0; ks < 4; ++ks) {
            const int col = ks * 8 + tig;
            uint32_t a[4][4];
            #pragma unroll
            for (int mt = 0; mt < 4; ++mt) {
                int r = wm * 64 + mt * 16 + gid;
                a[mt][0] = __float_as_uint(Ab[col * PADK + r]);
                a[mt][1] = __float_as_uint(Ab[col * PADK + r + 8]);
                a[mt][2] = __float_as_uint(Ab[(col + 4) * PADK + r]);
                a[mt][3] = __float_as_uint(Ab[(col + 4) * PADK + r + 8]);
            }
            #pragma unroll
            for (int nt = 0; nt < 4; ++nt) {
                int n = wn * 32 + nt * 8 + gid;
                uint32_t b0 = __float_as_uint(Bb[n * PADR + col]);
                uint32_t b1 = __float_as_uint(Bb[n * PADR + col + 4]);
                #pragma unroll
                for (int mt = 0; mt < 4; ++mt)
                    mma_tf32_16n8k8(acc[mt][nt],
                                    a[mt][0], a[mt][1], a[mt][2], a[mt][3],
                                    b0, b1);
            }
        }
    }

    #pragma unroll
    for (int mt = 0; mt < 4; ++mt) {
        int row = r0 + wm * 64 + mt * 16 + gid;
        #pragma unroll
        for (int nt = 0; nt < 4; ++nt) {
            int co = co0 + wn * 32 + nt * 8 + tig * 2;
            float bs0 = bias[co], bs1 = bias[co + 1];
            __nv_bfloat162 v0, v1;
            v0.x = __float2bfloat16(acc[mt][nt][0] + bs0);
            v0.y = __float2bfloat16(acc[mt][nt][1] + bs1);
            v1.x = __float2bfloat16(acc[mt][nt][2] + bs0);
            v1.y = __float2bfloat16(acc[mt][nt][3] + bs1);
            *(__nv_bfloat162*)&out[(size_t)row * CC + co]       = v0;
            *(__nv_bfloat162*)&out[(size_t)(row + 8) * CC + co] = v1;
        }
    }
}

// ============================================================================
// Kernel 2: PERSISTENT fused scores + per-image max (bf16 mma + ldmatrix).
//   grid = 304 blocks (2/SM), each streams 13-14 items of
//   (qt, img, nt) = 128 q x 128 keys x K512 = 16 K-chunks through one
//   continuous 3-stage cp.async ring (no drain at item boundaries).
//   Per-item epilogue: reduce + orderable-uint atomicMax into g_pmaxu.
// ============================================================================
#define PB 40                         // bf16 elems per smem row (32 + 8 pad)
#define SC_TILE_B (128 * PB * 2)      // 10240 bytes (A or B tile)
#define SC_STAGE_B (2 * SC_TILE_B)    // 20480
#define SC_RED_OFF (3 * SC_STAGE_B)   // 61440
#define SC_SMEM (SC_RED_OFF + 512 * 4)
#define N_ITEMS 4096                  // 64 qt x 8 img x 8 nt
#define GRID_SC 304

__global__ __launch_bounds__(256, 2) void scores_mma_kernel()
{
    extern __shared__ char smc[];
    const uint32_t sbase = smem_u32(smc);

    const int t    = threadIdx.x;
    const int lane = t & 31;
    const int wid  = t >> 5;
    const int wm   = wid >> 2;
    const int wn   = wid & 3;
    const int gid  = lane >> 2;
    const int tig  = lane & 3;
    const int blk  = blockIdx.x;

    const int n_items  = (N_ITEMS - blk + GRID_SC - 1) / GRID_SC;
    const int n_chunks = n_items * 16;

    float* red = (float*)(smc + SC_RED_OFF);

    // ldmatrix lane address components
    const int lrow = lane & 15;
    const int lseg = (lane >> 4) * 8;

    auto issue = [&](int gc) {
        const int it  = blk + (gc >> 4) * GRID_SC;
        const int k0  = (gc & 15) * SBK;
        const int s   = gc % 3;
        const __nv_bfloat16* qp = g_q + (size_t)(it >> 6) * 128 * CC;
        const __nv_bfloat16* kp = g_k +
            (size_t)((((it >> 3) & 7) * HWD) + (it & 7) * 128) * CC;
        uint32_t As = sbase + (uint32_t)(s * SC_STAGE_B);
        #pragma unroll
        for (int u = 0; u < 2; u++) {
            int f = t + u * 256, r = f & 127, seg = f >> 7;   // conflict-free STS
            cp_cg16(As + (uint32_t)(r * PB + seg * 8) * 2,
                    qp + (size_t)r * CC + k0 + seg * 8);
        }
        uint32_t Bs = As + SC_TILE_B;
        #pragma unroll
        for (int u = 0; u < 2; u++) {
            int f = t + u * 256, r = f & 127, seg = f >> 7;
            cp_cg16(Bs + (uint32_t)(r * PB + seg * 8) * 2,
                    kp + (size_t)r * CC + k0 + seg * 8);
        }
        cp_commit();
    };

    float acc[4][4][4];

    issue(0); issue(1);
    for (int gc = 0; gc < n_chunks; ++gc) {
        if ((gc & 15) == 0) {
            #pragma unroll
            for (int mt = 0; mt < 4; mt++)
                #pragma unroll
                for (int nt = 0; nt < 4; nt++)
                    #pragma unroll
                    for (int v = 0; v < 4; v++) acc[mt][nt][v] = 0.f;
        }
        if (gc < n_chunks - 1) cp_wait<1>(); else cp_wait<0>();
        __syncthreads();
        if (gc + 2 < n_chunks) issue(gc + 2);

        const uint32_t Ab = sbase + (uint32_t)((gc % 3) * SC_STAGE_B);
        const uint32_t Bb = Ab + SC_TILE_B;

        #pragma unroll
        for (int ks = 0; ks < 2; ++ks) {
            const int kcol = ks * 16 + lseg;
            uint32_t a[4][4];
            #pragma unroll
            for (int mt = 0; mt < 4; ++mt)
                ldm_x4(a[mt], Ab + (uint32_t)((wm * 64 + mt * 16 + lrow) * PB + kcol) * 2);
            uint32_t bf[2][4];
            #pragma unroll
            for (int nh = 0; nh < 2; ++nh)
                ldm_x4(bf[nh], Bb + (uint32_t)((wn * 32 + nh * 16 + lrow) * PB + kcol) * 2);
            #pragma unroll
            for (int nt = 0; nt < 4; ++nt) {
                uint32_t b0 = bf[nt >> 1][nt & 1];
                uint32_t b1 = bf[nt >> 1][(nt & 1) + 2];
                #pragma unroll
                for (int mt = 0; mt < 4; ++mt)
                    mma_bf16_16n8k16(acc[mt][nt], a[mt], b0, b1);
            }
        }

        if ((gc & 15) == 15) {
            #pragma unroll
            for (int mt = 0; mt < 4; ++mt) {
                float m0 = -1e30f, m1 = -1e30f;
                #pragma unroll
                for (int nt = 0; nt < 4; ++nt) {
                    m0 = fmaxf(m0, fmaxf(acc[mt][nt][0], acc[mt][nt][1]));
                    m1 = fmaxf(m1, fmaxf(acc[mt][nt][2], acc[mt][nt][3]));
                }
                m0 = fmaxf(m0, __shfl_xor_sync(0xffffffffu, m0, 1));
                m0 = fmaxf(m0, __shfl_xor_sync(0xffffffffu, m0, 2));
                m1 = fmaxf(m1, __shfl_xor_sync(0xffffffffu, m1, 1));
                m1 = fmaxf(m1, __shfl_xor_sync(0xffffffffu, m1, 2));
                if (tig == 0) {
                    int r = wm * 64 + mt * 16 + gid;
                    red[wn * 128 + r]     = m0;
                    red[wn * 128 + r + 8] = m1;
                }
            }
            __syncthreads();
            if (t < 128) {
                float v = fmaxf(fmaxf(red[t], red[128 + t]),
                                fmaxf(red[256 + t], red[384 + t]));
                int it  = blk + (gc >> 4) * GRID_SC;
                int qt  = it >> 6;
                int img = (it >> 3) & 7;
                atomicMax(&g_pmaxu[(size_t)(qt * 128 + t) * BB + img], fenc(v));
            }
            __syncthreads();
        }
    }
}

// ============================================================================
// Kernel 3: logits = mean-over-images(pmax) / sqrt(C); softmax per batch.
// ============================================================================
__global__ __launch_bounds__(256) void softmax_kernel()
{
    const int b = blockIdx.x;
    const int t = threadIdx.x;
    __shared__ float smr[256];
    __shared__ float logits[HWD];
    const float scale = 1.0f / sqrtf((float)CC);

    float lmax = -1e30f;
    for (int p = t; p < HWD; p += 256) {
        float s = 0.f;
        #pragma unroll
        for (int img = 0; img < BB; img++)
            s += fdec(g_pmaxu[(size_t)(b * HWD + p) * BB + img]);
        float lg = s * (1.0f / BB) * scale;
        logits[p] = lg;
        lmax = fmaxf(lmax, lg);
    }
    smr[t] = lmax; __syncthreads();
    for (int s = 128; s > 0; s >>= 1) {
        if (t < s) smr[t] = fmaxf(smr[t], smr[t + s]);
        __syncthreads();
    }
    float gmax = smr[0]; __syncthreads();

    float lsum = 0.f;
    for (int p = t; p < HWD; p += 256) {
        float e = expf(logits[p] - gmax);
        logits[p] = e;
        lsum += e;
    }
    smr[t] = lsum; __syncthreads();
    for (int s = 128; s > 0; s >>= 1) {
        if (t < s) smr[t] += smr[t + s];
        __syncthreads();
    }
    float inv = 1.0f / smr[0];
    for (int p = t; p < HWD; p += 256)
        g_w[b * HWD + p] = logits[p] * inv;
}

// ============================================================================
// Kernel 4: gated output conv, 2-term tf32 split (Ahi.Bhi + Ahi.Blo).
//   grid (4, 8, 8). 2 CTAs/SM.
// ============================================================================
__global__ __launch_bounds__(256, 2) void outconv_tc_kernel(
    const float* __restrict__ x, const float* __restrict__ W6,
    const float* __restrict__ b6, float* __restrict__ out)
{
    extern __shared__ float sm[];
    const uint32_t sbase = smem_u32(sm);

    const int t    = threadIdx.x;
    const int lane = t & 31;
    const int wid  = t >> 5;
    const int wm   = wid >> 2;
    const int wn   = wid & 3;
    const int gid  = lane >> 2;
    const int tig  = lane & 3;

    const int co0 = blockIdx.x * 128;
    const int p0  = blockIdx.y * 128;
    const int b   = blockIdx.z;
    const float* xb = x + (size_t)b * CC * HWD;

    auto issue = [&](int c) {
        const int s  = c % 3;
        const int k0 = c * SBK;
        uint32_t As = sbase + (uint32_t)(s * PJ_B_F) * 4;      // [co][k] PADR
        #pragma unroll
        for (int u = 0; u < 4; u++) {
            int f = t + u * 256, m = f >> 3, c4 = (f & 7) * 4;
            cp_cg16(As + (uint32_t)(m * PADR + c4) * 4,
                    W6 + (size_t)(co0 + m) * CC + k0 + c4);
        }
        uint32_t Bs = sbase + (uint32_t)(3 * PJ_B_F + s * PJ_A_F) * 4;  // [k][p] PADK
        #pragma unroll
        for (int u = 0; u < 4; u++) {
            int f = t + u * 256, kk = f >> 5, p4 = (f & 31) * 4;
            cp_cg16(Bs + (uint32_t)(kk * PADK + p4) * 4,
                    xb + (size_t)(k0 + kk) * HWD + p0 + p4);
        }
        cp_commit();
    };

    float acc[4][4][4];
    #pragma unroll
    for (int mt = 0; mt < 4; mt++)
        #pragma unroll
        for (int nt = 0; nt < 4; nt++)
            #pragma unroll
            for (int v = 0; v < 4; v++) acc[mt][nt][v] = 0.f;

    issue(0); issue(1);
    for (int c = 0; c < 16; ++c) {
        if (c < 15) cp_wait<1>(); else cp_wait<0>();
        __syncthreads();
        if (c + 2 < 16) issue(c + 2);

        const float* Ab = sm + (c % 3) * PJ_B_F;                 // [co][k]
        const float* Bb = sm + 3 * PJ_B_F + (c % 3) * PJ_A_F;    // [k][p]

        #pragma unroll
        for (int ks = 0; ks < 4; ++ks) {
            const int col = ks * 8 + tig;
            uint32_t ah[4][4];
            #pragma unroll
            for (int mt = 0; mt < 4; ++mt) {
                int m = wm * 64 + mt * 16 + gid;
                ah[mt][0] = __float_as_uint(Ab[m * PADR + col])           & 0xFFFFE000u;
                ah[mt][1] = __float_as_uint(Ab[(m + 8) * PADR + col])     & 0xFFFFE000u;
                ah[mt][2] = __float_as_uint(Ab[m * PADR + col + 4])       & 0xFFFFE000u;
                ah[mt][3] = __float_as_uint(Ab[(m + 8) * PADR + col + 4]) & 0xFFFFE000u;
            }
            #pragma unroll
            for (int nt = 0; nt < 4; ++nt) {
                int n = wn * 32 + nt * 8 + gid;
                uint32_t bh0, bl0, bh1, bl1;
                tf32_split(Bb[col * PADK + n],       bh0, bl0);
                tf32_split(Bb[(col + 4) * PADK + n], bh1, bl1);
                #pragma unroll
                for (int mt = 0; mt < 4; ++mt) {
                    mma_tf32_16n8k8(acc[mt][nt],
                                    ah[mt][0], ah[mt][1], ah[mt][2], ah[mt][3],
                                    bh0, bh1);
                    mma_tf32_16n8k8(acc[mt][nt],
                                    ah[mt][0], ah[mt][1], ah[mt][2], ah[mt][3],
                                    bl0, bl1);
                }
            }
        }
    }

    #pragma unroll
    for (int mt = 0; mt < 4; ++mt) {
        int co = co0 + wm * 64 + mt * 16 + gid;
        float bs0 = b6[co], bs1 = b6[co + 8];
        #pragma unroll
        for (int nt = 0; nt < 4; ++nt) {
            int p = p0 + wn * 32 + nt * 8 + tig * 2;
            float g0 = g_w[b * HWD + p];
            float g1 = g_w[b * HWD + p + 1];
            float2 o0 = { acc[mt][nt][0] * g0 + bs0, acc[mt][nt][1] * g1 + bs0 };
            float2 o1 = { acc[mt][nt][2] * g0 + bs1, acc[mt][nt][3] * g1 + bs1 };
            *(float2*)&out[((size_t)(b * CC + co)) * HWD + p]     = o0;
            *(float2*)&out[((size_t)(b * CC + co + 8)) * HWD + p] = o1;
        }
    }
}

// ============================================================================
extern "C" void kernel_launch(void* const* d_in, const int* in_sizes, int n_in,
                              void* d_out, int out_size)
{
    const float* x  = (const float*)d_in[0];
    const float* Wq = (const float*)d_in[1];
    const float* bq = (const float*)d_in[2];
    const float* Wk = (const float*)d_in[3];
    const float* bk = (const float*)d_in[4];
    const float* W6 = (const float*)d_in[5];
    const float* b6 = (const float*)d_in[6];
    float* out = (float*)d_out;

    cudaFuncSetAttribute(proj_tc_kernel,
                         cudaFuncAttributeMaxDynamicSharedMemorySize, PJ_SMEM);
    cudaFuncSetAttribute(scores_mma_kernel,
                         cudaFuncAttributeMaxDynamicSharedMemorySize, SC_SMEM);
    cudaFuncSetAttribute(outconv_tc_kernel,
                         cudaFuncAttributeMaxDynamicSharedMemorySize, PJ_SMEM);

    dim3 blk(256);
    proj_tc_kernel<<<dim3(RR / 128, CC / 128, 2), blk, PJ_SMEM>>>(x, Wq, bq, Wk, bk);
    scores_mma_kernel<<<GRID_SC, blk, SC_SMEM>>>();
    softmax_kernel<<<BB, blk>>>();
    outconv_tc_kernel<<<dim3(CC / 128, HWD / 128, BB), blk, PJ_SMEM>>>(x, W6, b6, out);
}